// round 15
// baseline (speedup 1.0000x reference)
#include <cuda_runtime.h>
#include <cuda_fp16.h>
#include <cmath>
#include <stdint.h>

#define NLEV   16
#define NDENSE 5
#define TSIZE  (1u << 19)
#define HID    64
#define ENC    32
#define P2     2654435761u
#define P3     805459861u
#define NMAX   1048576
#define NBINS  32768

#define BLK    256          // threads per CTA
#define PTS    512          // points per CTA (2 per thread)
#define SCALE_F    8192.0f  // 2^13: enc/h stored scaled in fp16
#define INV_SCALE  (1.0f / 8192.0f)

typedef unsigned long long u64;

// ---- device scratch (static, no runtime allocation) ----
#define QCAP 339072
__device__ float4 g_Q[QCAP];          // dense-level x-pair tables
__device__ int    g_hist[NBINS];      // morton histogram / running offsets
__device__ float4 g_xs[NMAX];         // sorted (x01, y01, z01, orig_idx)

struct LevelParams {
    float    resf[NLEV];
    unsigned s1[NLEV];
    unsigned s2[NLEV];
    unsigned qoff[NDENSE];
    unsigned qcnt[NDENSE];
};

__device__ __forceinline__ u64 pk2(float a, float b) {
    u64 r; asm("mov.b64 %0, {%1,%2};" : "=l"(r) : "f"(a), "f"(b)); return r;
}
__device__ __forceinline__ void upk2(u64 v, float& a, float& b) {
    asm("mov.b64 {%0,%1}, %2;" : "=f"(a), "=f"(b) : "l"(v));
}
// Blackwell packed fp32 FMA (FFMA2), only reachable via PTX.
__device__ __forceinline__ u64 ffma2(u64 a, u64 b, u64 c) {
    u64 d; asm("fma.rn.f32x2 %0, %1, %2, %3;" : "=l"(d) : "l"(a), "l"(b), "l"(c)); return d;
}

// ---------- morton helpers ----------
__device__ __forceinline__ unsigned part3(unsigned v) {
    v &= 31u;
    unsigned r = 0;
#pragma unroll
    for (int b = 0; b < 5; b++) r |= ((v >> b) & 1u) << (3 * b);
    return r;
}
__device__ __forceinline__ unsigned morton_bin(float x0, float y0, float z0) {
    unsigned bx = min(31, max(0, (int)floorf(x0 * 32.0f)));
    unsigned by = min(31, max(0, (int)floorf(y0 * 32.0f)));
    unsigned bz = min(31, max(0, (int)floorf(z0 * 32.0f)));
    return part3(bx) | (part3(by) << 1) | (part3(bz) << 2);
}

// ---------- launch 1: fused morton histogram + dense pair-table build ----------
__global__ void bin_and_buildq(const float* __restrict__ x,
                               const float2* __restrict__ tables,
                               LevelParams lp, int npts, unsigned qtotal) {
    const unsigned i = blockIdx.x * blockDim.x + threadIdx.x;
    if (i < qtotal) {
        int l = 0; unsigned base = 0;
#pragma unroll
        for (int k = 0; k < NDENSE; k++) {
            unsigned o = lp.qoff[k];
            if (i >= o && i < o + lp.qcnt[k]) { l = k; base = o; }
        }
        const unsigned j = i - base;
        const float2* __restrict__ tab = tables + (size_t)l * TSIZE;
        float2 a = __ldg(&tab[j]);
        float2 b = __ldg(&tab[j + 1]);
        g_Q[i] = make_float4(a.x, a.y, b.x, b.y);
    }
    if ((int)i < npts) {
        float x0 = (x[3 * i + 0] + 1.0f) * 0.5f;
        float y0 = (x[3 * i + 1] + 1.0f) * 0.5f;
        float z0 = (x[3 * i + 2] + 1.0f) * 0.5f;
        atomicAdd(&g_hist[morton_bin(x0, y0, z0)], 1);
    }
}

// ---------- launch 2: exclusive prefix sum over NBINS ----------
__global__ void scan_bins() {
    __shared__ int warp_tot[32];
    const int t = threadIdx.x;
    const int base = t * (NBINS / 1024);
    int loc[NBINS / 1024];
    int ts = 0;
#pragma unroll
    for (int k = 0; k < NBINS / 1024; k++) { loc[k] = g_hist[base + k]; ts += loc[k]; }
    int v = ts;
    for (int d = 1; d < 32; d <<= 1) {
        int n = __shfl_up_sync(0xffffffffu, v, d);
        if ((t & 31) >= d) v += n;
    }
    if ((t & 31) == 31) warp_tot[t >> 5] = v;
    __syncthreads();
    if (t < 32) {
        int w = warp_tot[t];
        for (int d = 1; d < 32; d <<= 1) {
            int n = __shfl_up_sync(0xffffffffu, w, d);
            if (t >= d) w += n;
        }
        warp_tot[t] = w;
    }
    __syncthreads();
    int excl = v - ts + ((t >> 5) ? warp_tot[(t >> 5) - 1] : 0);
    int run = excl;
#pragma unroll
    for (int k = 0; k < NBINS / 1024; k++) { g_hist[base + k] = run; run += loc[k]; }
}

// ---------- launch 3: scatter ----------
__global__ void scatter_points(const float* __restrict__ x, int npts) {
    int p = blockIdx.x * blockDim.x + threadIdx.x;
    if (p >= npts) return;
    float x0 = (x[3 * p + 0] + 1.0f) * 0.5f;
    float y0 = (x[3 * p + 1] + 1.0f) * 0.5f;
    float z0 = (x[3 * p + 2] + 1.0f) * 0.5f;
    int pos = atomicAdd(&g_hist[morton_bin(x0, y0, z0)], 1);
    g_xs[pos] = make_float4(x0, y0, z0, __int_as_float(p));
}

// ---------- hashed-level issue/consume split ----------
__device__ __forceinline__ void hashed_issue(
    float x0, float y0, float z0, float rf,
    const float2* __restrict__ tab2, const float4* __restrict__ tab4, unsigned m,
    float& fx, float& fy, float& fz, float4 q[4], unsigned& sel)
{
    const float px = x0 * rf, py = y0 * rf, pz = z0 * rf;
    const float fpx = floorf(px), fpy = floorf(py), fpz = floorf(pz);
    fx = px - fpx; fy = py - fpy; fz = pz - fpz;
    const unsigned cx = (unsigned)fpx;
    const unsigned ay = (unsigned)fpy * P2, az = (unsigned)fpz * P3;
    const unsigned s[4] = {ay ^ az, ay ^ (az + P3),
                           (ay + P2) ^ az, (ay + P2) ^ (az + P3)};
    sel = 0u;
    if ((cx & 1u) == 0u) {
#pragma unroll
        for (int j = 0; j < 4; j++) {
            const unsigned i0 = (cx ^ s[j]) & m;
            q[j] = __ldg(&tab4[i0 >> 1]);
            sel |= (i0 & 1u) << j;
        }
    } else {
        const unsigned cx1 = cx + 1u;
#pragma unroll
        for (int j = 0; j < 4; j++) {
            const float2 a = __ldg(&tab2[(cx ^ s[j]) & m]);
            const float2 b = __ldg(&tab2[(cx1 ^ s[j]) & m]);
            q[j] = make_float4(a.x, a.y, b.x, b.y);
        }
    }
}

// Consume: hi/lo selects deferred here; enc written SCALED into fp16 smem.
__device__ __forceinline__ void hashed_consume(
    float fx, float fy, float fz, const float4 q[4], unsigned sel,
    __half2* __restrict__ dst)
{
    const float gxS = (1.0f - fx) * SCALE_F, fxS = fx * SCALE_F;
    const float gy = 1.0f - fy, gz = 1.0f - fz;
    const float wyz[4] = {gy * gz, gy * fz, fy * gz, fy * fz};
    float e0 = 0.0f, e1 = 0.0f;
#pragma unroll
    for (int j = 0; j < 4; j++) {
        const bool hi = (sel >> j) & 1u;
        const float a0 = hi ? q[j].z : q[j].x;
        const float a1 = hi ? q[j].w : q[j].y;
        const float b0 = hi ? q[j].x : q[j].z;
        const float b1 = hi ? q[j].y : q[j].w;
        const float w0 = wyz[j] * gxS, w1 = wyz[j] * fxS;
        e0 = fmaf(w0, a0, fmaf(w1, b0, e0));
        e1 = fmaf(w0, a1, fmaf(w1, b1, e1));
    }
    *dst = __floats2half2_rn(e0, e1);
}

// ---------- launch 4: main fused kernel (256 thr, 2 pts/thread, 16 warps/SM) ----------
__global__ void __launch_bounds__(BLK, 2) sdf_fused(
    const float* __restrict__ tables,
    const float* __restrict__ W0,
    const float* __restrict__ W1,
    const float* __restrict__ W2,
    float* __restrict__ out,
    int npts, LevelParams lp)
{
    extern __shared__ __align__(16) float smem[];
    float*   sW0 = smem;                       // 2048 floats
    float*   sW1 = sW0 + ENC * HID;            // 4096
    float*   sW2 = sW1 + HID * HID;            // 64
    __half2* sH2 = (__half2*)(sW2 + HID);      // 32 rows x 512 half2 = 64KB

    {
        int t = threadIdx.x;
        float4*       s0 = (float4*)sW0;  const float4* g0 = (const float4*)W0;
        for (int i = t; i < ENC * HID / 4; i += BLK) s0[i] = g0[i];
        float4*       s1 = (float4*)sW1;  const float4* g1 = (const float4*)W1;
        for (int i = t; i < HID * HID / 4; i += BLK) s1[i] = g1[i];
        if (t < HID / 4) ((float4*)sW2)[t] = ((const float4*)W2)[t];
    }
    __syncthreads();

    const int t = threadIdx.x;
    const int base = blockIdx.x * PTS;
    const int ptA = base + t;
    const int ptB = base + BLK + t;
    const bool vA = ptA < npts, vB = ptB < npts;

    const float4 xsA = g_xs[vA ? ptA : 0];
    const float4 xsB = g_xs[vB ? ptB : 0];
    const int origA = vA ? __float_as_int(xsA.w) : -1;
    const int origB = vB ? __float_as_int(xsB.w) : -1;
    const float xA = xsA.x, yA = xsA.y, zA = xsA.z;
    const float xB = xsB.x, yB = xsB.y, zB = xsB.z;

    // ================= dense levels: A+B interleaved per level =================
#pragma unroll
    for (int l = 0; l < NDENSE; l++) {
        const float rf = lp.resf[l];
        const unsigned s1 = lp.s1[l], s2 = lp.s2[l];
        const float4* __restrict__ Q = g_Q + lp.qoff[l];

        const float pxA = xA * rf, pyA = yA * rf, pzA = zA * rf;
        const float fpxA = floorf(pxA), fpyA = floorf(pyA), fpzA = floorf(pzA);
        const float fxA = pxA - fpxA, fyA = pyA - fpyA, fzA = pzA - fpzA;
        const unsigned bA0 = (unsigned)fpxA + (unsigned)fpyA * s1 + (unsigned)fpzA * s2;
        const float pxB = xB * rf, pyB = yB * rf, pzB = zB * rf;
        const float fpxB = floorf(pxB), fpyB = floorf(pyB), fpzB = floorf(pzB);
        const float fxB = pxB - fpxB, fyB = pyB - fpyB, fzB = pzB - fpzB;
        const unsigned bB0 = (unsigned)fpxB + (unsigned)fpyB * s1 + (unsigned)fpzB * s2;

        const unsigned bbA[4] = {bA0, bA0 + s2, bA0 + s1, bA0 + s1 + s2};
        const unsigned bbB[4] = {bB0, bB0 + s2, bB0 + s1, bB0 + s1 + s2};

        float4 qA[4], qB[4];
#pragma unroll
        for (int j = 0; j < 4; j++) qA[j] = __ldg(&Q[bbA[j]]);
#pragma unroll
        for (int j = 0; j < 4; j++) qB[j] = __ldg(&Q[bbB[j]]);

        {
            const float gxS = (1.0f - fxA) * SCALE_F, fxS = fxA * SCALE_F;
            const float gy = 1.0f - fyA, gz = 1.0f - fzA;
            const float wyz[4] = {gy * gz, gy * fzA, fyA * gz, fyA * fzA};
            float e0 = 0.0f, e1 = 0.0f;
#pragma unroll
            for (int j = 0; j < 4; j++) {
                const float w0 = wyz[j] * gxS, w1 = wyz[j] * fxS;
                e0 = fmaf(w0, qA[j].x, fmaf(w1, qA[j].z, e0));
                e1 = fmaf(w0, qA[j].y, fmaf(w1, qA[j].w, e1));
            }
            sH2[l * PTS + t] = __floats2half2_rn(e0, e1);
        }
        {
            const float gxS = (1.0f - fxB) * SCALE_F, fxS = fxB * SCALE_F;
            const float gy = 1.0f - fyB, gz = 1.0f - fzB;
            const float wyz[4] = {gy * gz, gy * fzB, fyB * gz, fyB * fzB};
            float e0 = 0.0f, e1 = 0.0f;
#pragma unroll
            for (int j = 0; j < 4; j++) {
                const float w0 = wyz[j] * gxS, w1 = wyz[j] * fxS;
                e0 = fmaf(w0, qB[j].x, fmaf(w1, qB[j].z, e0));
                e1 = fmaf(w0, qB[j].y, fmaf(w1, qB[j].w, e1));
            }
            sH2[l * PTS + BLK + t] = __floats2half2_rn(e0, e1);
        }
    }

    // ========== hashed levels: single level, A+B interleaved (8 loads in flight) ====
    {
        const unsigned m = TSIZE - 1u;
#pragma unroll 1
        for (int l = NDENSE; l < NLEV; l++) {
            const float rf = lp.resf[l];
            const float2* __restrict__ t2 = ((const float2*)tables) + (size_t)l * TSIZE;
            const float4* __restrict__ t4 = (const float4*)t2;

            float fxA0, fyA0, fzA0, fxB0, fyB0, fzB0;
            float4 qA0[4], qB0[4];
            unsigned sA0, sB0;

            hashed_issue(xA, yA, zA, rf, t2, t4, m, fxA0, fyA0, fzA0, qA0, sA0);
            hashed_issue(xB, yB, zB, rf, t2, t4, m, fxB0, fyB0, fzB0, qB0, sB0);

            hashed_consume(fxA0, fyA0, fzA0, qA0, sA0, &sH2[l * PTS + t]);
            hashed_consume(fxB0, fyB0, fzB0, qB0, sB0, &sH2[l * PTS + BLK + t]);
        }
    }

    // ================= layer 0: weight-shared across both points =================
    u64 accA[HID / 2], accB[HID / 2];
#pragma unroll
    for (int j = 0; j < HID / 2; j++) { accA[j] = 0ull; accB[j] = 0ull; }

#pragma unroll 2
    for (int l = 0; l < NLEV; l++) {
        const float2 eA = __half22float2(sH2[l * PTS + t]);
        const float2 eB = __half22float2(sH2[l * PTS + BLK + t]);
        const u64 aA0 = pk2(eA.x, eA.x), aA1 = pk2(eA.y, eA.y);
        const u64 aB0 = pk2(eB.x, eB.x), aB1 = pk2(eB.y, eB.y);
        const ulonglong2* __restrict__ r0 = (const ulonglong2*)&sW0[(2 * l) * HID];
        const ulonglong2* __restrict__ r1 = (const ulonglong2*)&sW0[(2 * l + 1) * HID];
#pragma unroll
        for (int j = 0; j < HID / 4; j++) {
            const ulonglong2 v0 = r0[j];
            const ulonglong2 v1 = r1[j];
            accA[2 * j]     = ffma2(aA1, v1.x, ffma2(aA0, v0.x, accA[2 * j]));
            accA[2 * j + 1] = ffma2(aA1, v1.y, ffma2(aA0, v0.y, accA[2 * j + 1]));
            accB[2 * j]     = ffma2(aB1, v1.x, ffma2(aB0, v0.x, accB[2 * j]));
            accB[2 * j + 1] = ffma2(aB1, v1.y, ffma2(aB0, v0.y, accB[2 * j + 1]));
        }
    }

    // ReLU -> h into smem as half2 (still scaled; threads touch only own columns)
#pragma unroll
    for (int j = 0; j < HID / 2; j++) {
        float a, b; upk2(accA[j], a, b);
        sH2[j * PTS + t] = __floats2half2_rn(fmaxf(a, 0.0f), fmaxf(b, 0.0f));
        upk2(accB[j], a, b);
        sH2[j * PTS + BLK + t] = __floats2half2_rn(fmaxf(a, 0.0f), fmaxf(b, 0.0f));
        accA[j] = 0ull; accB[j] = 0ull;
    }

    // ================= layer 1: weight-shared across both points =================
#pragma unroll 2
    for (int i = 0; i < HID / 2; i++) {
        const float2 hA = __half22float2(sH2[i * PTS + t]);
        const float2 hB = __half22float2(sH2[i * PTS + BLK + t]);
        const u64 aA0 = pk2(hA.x, hA.x), aA1 = pk2(hA.y, hA.y);
        const u64 aB0 = pk2(hB.x, hB.x), aB1 = pk2(hB.y, hB.y);
        const ulonglong2* __restrict__ r0 = (const ulonglong2*)&sW1[(2 * i) * HID];
        const ulonglong2* __restrict__ r1 = (const ulonglong2*)&sW1[(2 * i + 1) * HID];
#pragma unroll
        for (int j = 0; j < HID / 4; j++) {
            const ulonglong2 v0 = r0[j];
            const ulonglong2 v1 = r1[j];
            accA[2 * j]     = ffma2(aA1, v1.x, ffma2(aA0, v0.x, accA[2 * j]));
            accA[2 * j + 1] = ffma2(aA1, v1.y, ffma2(aA0, v0.y, accA[2 * j + 1]));
            accB[2 * j]     = ffma2(aB1, v1.x, ffma2(aB0, v0.x, accB[2 * j]));
            accB[2 * j + 1] = ffma2(aB1, v1.y, ffma2(aB0, v0.y, accB[2 * j + 1]));
        }
    }

    // ================= ReLU + layer 2 (undo the 2^13 scale once) =================
    float resA = 0.0f, resB = 0.0f;
    const float2* w2p = (const float2*)sW2;
#pragma unroll
    for (int j = 0; j < HID / 2; j++) {
        const float2 w = w2p[j];
        float a, b; upk2(accA[j], a, b);
        resA = fmaf(fmaxf(a, 0.0f), w.x, resA);
        resA = fmaf(fmaxf(b, 0.0f), w.y, resA);
        upk2(accB[j], a, b);
        resB = fmaf(fmaxf(a, 0.0f), w.x, resB);
        resB = fmaf(fmaxf(b, 0.0f), w.y, resB);
    }
    if (origA >= 0) out[origA] = resA * INV_SCALE;
    if (origB >= 0) out[origB] = resB * INV_SCALE;
}

static LevelParams make_params(unsigned* qtotal_out) {
    LevelParams lp;
    unsigned qoff = 0;
    for (int l = 0; l < NLEV; l++) {
        const double r = floor(16.0 * pow(1.3819, (double)l));
        const int res = (int)r;
        lp.resf[l] = (float)res;
        const unsigned s1 = (unsigned)(res + 1);
        lp.s1[l] = s1;
        lp.s2[l] = s1 * s1;
        if (l < NDENSE) {
            const unsigned cnt = s1 * s1 * s1 + s1 * s1 + s1 + 2u;
            lp.qoff[l] = qoff;
            lp.qcnt[l] = cnt;
            qoff += cnt;
        }
    }
    *qtotal_out = qoff;
    return lp;
}

extern "C" void kernel_launch(void* const* d_in, const int* in_sizes, int n_in,
                              void* d_out, int out_size) {
    const float* x      = (const float*)d_in[0];
    const float* tables = (const float*)d_in[1];
    const float* W0     = (const float*)d_in[2];
    const float* W1     = (const float*)d_in[3];
    const float* W2     = (const float*)d_in[4];
    float* out = (float*)d_out;

    const int npts = out_size;
    unsigned qtotal = 0;
    LevelParams lp = make_params(&qtotal);

    static void* hist_addr = nullptr;
    if (!hist_addr) cudaGetSymbolAddress(&hist_addr, g_hist);

    // weights 24.25KB + 32 rows x 512 half2 = 64KB => 88.25KB; 2 CTAs x 256thr = 16 warps/SM
    const int smem_bytes = (ENC * HID + HID * HID + HID) * (int)sizeof(float)
                         + (HID / 2) * PTS * (int)sizeof(__half2);
    static bool attr_set = false;
    if (!attr_set) {
        cudaFuncSetAttribute(sdf_fused, cudaFuncAttributeMaxDynamicSharedMemorySize,
                             smem_bytes);
        attr_set = true;
    }

    cudaMemsetAsync(hist_addr, 0, NBINS * sizeof(int), 0);

    // 1: fused morton histogram + dense pair tables
    {
        const unsigned total = (unsigned)npts > qtotal ? (unsigned)npts : qtotal;
        bin_and_buildq<<<(total + 255) / 256, 256>>>(x, (const float2*)tables, lp,
                                                     npts, qtotal);
    }
    // 2: prefix sum
    scan_bins<<<1, 1024>>>();
    // 3: scatter (deterministic output: per-point results independent of
    //    intra-bin order)
    scatter_points<<<(npts + 255) / 256, 256>>>(x, npts);
    // 4: fused main
    const int grid = (npts + PTS - 1) / PTS;
    sdf_fused<<<grid, BLK, smem_bytes>>>(tables, W0, W1, W2, out, npts, lp);
}

// round 16
// speedup vs baseline: 3.1360x; 3.1360x over previous
#include <cuda_runtime.h>
#include <cuda_fp16.h>
#include <cmath>
#include <stdint.h>

#define NLEV   16
#define NDENSE 5
#define TSIZE  (1u << 19)
#define HID    64
#define ENC    32
#define P2     2654435761u
#define P3     805459861u
#define NMAX   1048576
#define NBINS  32768

#define BLK    256          // threads per CTA
#define PTS    512          // points per CTA (2 per thread)
#define SCALE_F    8192.0f  // 2^13: enc/h stored scaled in fp16
#define INV_SCALE  (1.0f / 8192.0f)

typedef unsigned long long u64;

// ---- device scratch (static, no runtime allocation) ----
#define QCAP 339072
__device__ float4 g_Q[QCAP];          // dense-level x-pair tables
__device__ int    g_hist[NBINS];      // morton histogram / running offsets
__device__ float4 g_xs[NMAX];         // sorted (x01, y01, z01, orig_idx)

struct LevelParams {
    float    resf[NLEV];
    unsigned s1[NLEV];
    unsigned s2[NLEV];
    unsigned qoff[NDENSE];
    unsigned qcnt[NDENSE];
};

__device__ __forceinline__ u64 pk2(float a, float b) {
    u64 r; asm("mov.b64 %0, {%1,%2};" : "=l"(r) : "f"(a), "f"(b)); return r;
}
__device__ __forceinline__ void upk2(u64 v, float& a, float& b) {
    asm("mov.b64 {%0,%1}, %2;" : "=f"(a), "=f"(b) : "l"(v));
}
// Blackwell packed fp32 FMA (FFMA2), only reachable via PTX.
__device__ __forceinline__ u64 ffma2(u64 a, u64 b, u64 c) {
    u64 d; asm("fma.rn.f32x2 %0, %1, %2, %3;" : "=l"(d) : "l"(a), "l"(b), "l"(c)); return d;
}

// ---------- morton helpers ----------
__device__ __forceinline__ unsigned part3(unsigned v) {
    v &= 31u;
    unsigned r = 0;
#pragma unroll
    for (int b = 0; b < 5; b++) r |= ((v >> b) & 1u) << (3 * b);
    return r;
}
__device__ __forceinline__ unsigned morton_bin(float x0, float y0, float z0) {
    unsigned bx = min(31, max(0, (int)floorf(x0 * 32.0f)));
    unsigned by = min(31, max(0, (int)floorf(y0 * 32.0f)));
    unsigned bz = min(31, max(0, (int)floorf(z0 * 32.0f)));
    return part3(bx) | (part3(by) << 1) | (part3(bz) << 2);
}

// ---------- launch 1: fused morton histogram + dense pair-table build ----------
__global__ void bin_and_buildq(const float* __restrict__ x,
                               const float2* __restrict__ tables,
                               LevelParams lp, int npts, unsigned qtotal) {
    const unsigned i = blockIdx.x * blockDim.x + threadIdx.x;
    if (i < qtotal) {
        int l = 0; unsigned base = 0;
#pragma unroll
        for (int k = 0; k < NDENSE; k++) {
            unsigned o = lp.qoff[k];
            if (i >= o && i < o + lp.qcnt[k]) { l = k; base = o; }
        }
        const unsigned j = i - base;
        const float2* __restrict__ tab = tables + (size_t)l * TSIZE;
        float2 a = __ldg(&tab[j]);
        float2 b = __ldg(&tab[j + 1]);
        g_Q[i] = make_float4(a.x, a.y, b.x, b.y);
    }
    if ((int)i < npts) {
        float x0 = (x[3 * i + 0] + 1.0f) * 0.5f;
        float y0 = (x[3 * i + 1] + 1.0f) * 0.5f;
        float z0 = (x[3 * i + 2] + 1.0f) * 0.5f;
        atomicAdd(&g_hist[morton_bin(x0, y0, z0)], 1);
    }
}

// ---------- launch 2: exclusive prefix sum over NBINS ----------
__global__ void scan_bins() {
    __shared__ int warp_tot[32];
    const int t = threadIdx.x;
    const int base = t * (NBINS / 1024);
    int loc[NBINS / 1024];
    int ts = 0;
#pragma unroll
    for (int k = 0; k < NBINS / 1024; k++) { loc[k] = g_hist[base + k]; ts += loc[k]; }
    int v = ts;
    for (int d = 1; d < 32; d <<= 1) {
        int n = __shfl_up_sync(0xffffffffu, v, d);
        if ((t & 31) >= d) v += n;
    }
    if ((t & 31) == 31) warp_tot[t >> 5] = v;
    __syncthreads();
    if (t < 32) {
        int w = warp_tot[t];
        for (int d = 1; d < 32; d <<= 1) {
            int n = __shfl_up_sync(0xffffffffu, w, d);
            if (t >= d) w += n;
        }
        warp_tot[t] = w;
    }
    __syncthreads();
    int excl = v - ts + ((t >> 5) ? warp_tot[(t >> 5) - 1] : 0);
    int run = excl;
#pragma unroll
    for (int k = 0; k < NBINS / 1024; k++) { g_hist[base + k] = run; run += loc[k]; }
}

// ---------- launch 3: scatter ----------
__global__ void scatter_points(const float* __restrict__ x, int npts) {
    int p = blockIdx.x * blockDim.x + threadIdx.x;
    if (p >= npts) return;
    float x0 = (x[3 * p + 0] + 1.0f) * 0.5f;
    float y0 = (x[3 * p + 1] + 1.0f) * 0.5f;
    float z0 = (x[3 * p + 2] + 1.0f) * 0.5f;
    int pos = atomicAdd(&g_hist[morton_bin(x0, y0, z0)], 1);
    g_xs[pos] = make_float4(x0, y0, z0, __int_as_float(p));
}

// ---------- hashed-level issue/consume split ----------
__device__ __forceinline__ void hashed_issue(
    float x0, float y0, float z0, float rf,
    const float2* __restrict__ tab2, const float4* __restrict__ tab4, unsigned m,
    float& fx, float& fy, float& fz, float4 q[4], unsigned& sel)
{
    const float px = x0 * rf, py = y0 * rf, pz = z0 * rf;
    const float fpx = floorf(px), fpy = floorf(py), fpz = floorf(pz);
    fx = px - fpx; fy = py - fpy; fz = pz - fpz;
    const unsigned cx = (unsigned)fpx;
    const unsigned ay = (unsigned)fpy * P2, az = (unsigned)fpz * P3;
    const unsigned s[4] = {ay ^ az, ay ^ (az + P3),
                           (ay + P2) ^ az, (ay + P2) ^ (az + P3)};
    sel = 0u;
    if ((cx & 1u) == 0u) {
#pragma unroll
        for (int j = 0; j < 4; j++) {
            const unsigned i0 = (cx ^ s[j]) & m;
            q[j] = __ldg(&tab4[i0 >> 1]);
            sel |= (i0 & 1u) << j;
        }
    } else {
        const unsigned cx1 = cx + 1u;
#pragma unroll
        for (int j = 0; j < 4; j++) {
            const float2 a = __ldg(&tab2[(cx ^ s[j]) & m]);
            const float2 b = __ldg(&tab2[(cx1 ^ s[j]) & m]);
            q[j] = make_float4(a.x, a.y, b.x, b.y);
        }
    }
}

// Consume: hi/lo selects deferred here; enc written SCALED into fp16 smem.
__device__ __forceinline__ void hashed_consume(
    float fx, float fy, float fz, const float4 q[4], unsigned sel,
    __half2* __restrict__ dst)
{
    const float gxS = (1.0f - fx) * SCALE_F, fxS = fx * SCALE_F;
    const float gy = 1.0f - fy, gz = 1.0f - fz;
    const float wyz[4] = {gy * gz, gy * fz, fy * gz, fy * fz};
    float e0 = 0.0f, e1 = 0.0f;
#pragma unroll
    for (int j = 0; j < 4; j++) {
        const bool hi = (sel >> j) & 1u;
        const float a0 = hi ? q[j].z : q[j].x;
        const float a1 = hi ? q[j].w : q[j].y;
        const float b0 = hi ? q[j].x : q[j].z;
        const float b1 = hi ? q[j].y : q[j].w;
        const float w0 = wyz[j] * gxS, w1 = wyz[j] * fxS;
        e0 = fmaf(w0, a0, fmaf(w1, b0, e0));
        e1 = fmaf(w0, a1, fmaf(w1, b1, e1));
    }
    *dst = __floats2half2_rn(e0, e1);
}

// ---- launch 4: main fused (256 thr, 2 pts/thread, CHUNKED MLP, 16 warps/SM) ----
__global__ void __launch_bounds__(BLK, 2) sdf_fused(
    const float* __restrict__ tables,
    const float* __restrict__ W0,
    const float* __restrict__ W1,
    const float* __restrict__ W2,
    float* __restrict__ out,
    int npts, LevelParams lp)
{
    extern __shared__ __align__(16) float smem[];
    float*   sW0 = smem;                       // 2048 floats
    float*   sW1 = sW0 + ENC * HID;            // 4096
    float*   sW2 = sW1 + HID * HID;            // 64
    __half2* sH2 = (__half2*)(sW2 + HID);      // 32 rows x 512 half2 = 64KB

    {
        int t = threadIdx.x;
        float4*       s0 = (float4*)sW0;  const float4* g0 = (const float4*)W0;
        for (int i = t; i < ENC * HID / 4; i += BLK) s0[i] = g0[i];
        float4*       s1 = (float4*)sW1;  const float4* g1 = (const float4*)W1;
        for (int i = t; i < HID * HID / 4; i += BLK) s1[i] = g1[i];
        if (t < HID / 4) ((float4*)sW2)[t] = ((const float4*)W2)[t];
    }
    __syncthreads();

    const int t = threadIdx.x;
    const int base = blockIdx.x * PTS;
    const int ptA = base + t;
    const int ptB = base + BLK + t;
    const bool vA = ptA < npts, vB = ptB < npts;

    const float4 xsA = g_xs[vA ? ptA : 0];
    const float4 xsB = g_xs[vB ? ptB : 0];
    const int origA = vA ? __float_as_int(xsA.w) : -1;
    const int origB = vB ? __float_as_int(xsB.w) : -1;
    const float xA = xsA.x, yA = xsA.y, zA = xsA.z;
    const float xB = xsB.x, yB = xsB.y, zB = xsB.z;

    // ================= dense levels: A+B interleaved per level =================
#pragma unroll
    for (int l = 0; l < NDENSE; l++) {
        const float rf = lp.resf[l];
        const unsigned s1 = lp.s1[l], s2 = lp.s2[l];
        const float4* __restrict__ Q = g_Q + lp.qoff[l];

        const float pxA = xA * rf, pyA = yA * rf, pzA = zA * rf;
        const float fpxA = floorf(pxA), fpyA = floorf(pyA), fpzA = floorf(pzA);
        const float fxA = pxA - fpxA, fyA = pyA - fpyA, fzA = pzA - fpzA;
        const unsigned bA0 = (unsigned)fpxA + (unsigned)fpyA * s1 + (unsigned)fpzA * s2;
        const float pxB = xB * rf, pyB = yB * rf, pzB = zB * rf;
        const float fpxB = floorf(pxB), fpyB = floorf(pyB), fpzB = floorf(pzB);
        const float fxB = pxB - fpxB, fyB = pyB - fpyB, fzB = pzB - fpzB;
        const unsigned bB0 = (unsigned)fpxB + (unsigned)fpyB * s1 + (unsigned)fpzB * s2;

        const unsigned bbA[4] = {bA0, bA0 + s2, bA0 + s1, bA0 + s1 + s2};
        const unsigned bbB[4] = {bB0, bB0 + s2, bB0 + s1, bB0 + s1 + s2};

        float4 qA[4], qB[4];
#pragma unroll
        for (int j = 0; j < 4; j++) qA[j] = __ldg(&Q[bbA[j]]);
#pragma unroll
        for (int j = 0; j < 4; j++) qB[j] = __ldg(&Q[bbB[j]]);

        {
            const float gxS = (1.0f - fxA) * SCALE_F, fxS = fxA * SCALE_F;
            const float gy = 1.0f - fyA, gz = 1.0f - fzA;
            const float wyz[4] = {gy * gz, gy * fzA, fyA * gz, fyA * fzA};
            float e0 = 0.0f, e1 = 0.0f;
#pragma unroll
            for (int j = 0; j < 4; j++) {
                const float w0 = wyz[j] * gxS, w1 = wyz[j] * fxS;
                e0 = fmaf(w0, qA[j].x, fmaf(w1, qA[j].z, e0));
                e1 = fmaf(w0, qA[j].y, fmaf(w1, qA[j].w, e1));
            }
            sH2[l * PTS + t] = __floats2half2_rn(e0, e1);
        }
        {
            const float gxS = (1.0f - fxB) * SCALE_F, fxS = fxB * SCALE_F;
            const float gy = 1.0f - fyB, gz = 1.0f - fzB;
            const float wyz[4] = {gy * gz, gy * fzB, fyB * gz, fyB * fzB};
            float e0 = 0.0f, e1 = 0.0f;
#pragma unroll
            for (int j = 0; j < 4; j++) {
                const float w0 = wyz[j] * gxS, w1 = wyz[j] * fxS;
                e0 = fmaf(w0, qB[j].x, fmaf(w1, qB[j].z, e0));
                e1 = fmaf(w0, qB[j].y, fmaf(w1, qB[j].w, e1));
            }
            sH2[l * PTS + BLK + t] = __floats2half2_rn(e0, e1);
        }
    }

    // ========== hashed levels: single level, A+B interleaved (8 loads in flight) ====
    {
        const unsigned m = TSIZE - 1u;
#pragma unroll 1
        for (int l = NDENSE; l < NLEV; l++) {
            const float rf = lp.resf[l];
            const float2* __restrict__ t2 = ((const float2*)tables) + (size_t)l * TSIZE;
            const float4* __restrict__ t4 = (const float4*)t2;

            float fxA0, fyA0, fzA0, fxB0, fyB0, fzB0;
            float4 qA0[4], qB0[4];
            unsigned sA0, sB0;

            hashed_issue(xA, yA, zA, rf, t2, t4, m, fxA0, fyA0, fzA0, qA0, sA0);
            hashed_issue(xB, yB, zB, rf, t2, t4, m, fxB0, fyB0, fzB0, qB0, sB0);

            hashed_consume(fxA0, fyA0, fzA0, qA0, sA0, &sH2[l * PTS + t]);
            hashed_consume(fxB0, fyB0, fzB0, qB0, sB0, &sH2[l * PTS + BLK + t]);
        }
    }

    // ================= layer 0: 2-pt weight-shared, 2 output chunks =================
    // enc rows 0..15; h chunk0 (out 0..31) -> rows 16..31; chunk1 -> rows 0..15.
    u64 acc[2][16];
#pragma unroll 1
    for (int s = 0; s < 2; s++) {
#pragma unroll
        for (int p = 0; p < 2; p++)
#pragma unroll
            for (int j = 0; j < 16; j++) acc[p][j] = 0ull;

#pragma unroll 2
        for (int er = 0; er < ENC / 2; er++) {
            float2 e[2];
#pragma unroll
            for (int p = 0; p < 2; p++)
                e[p] = __half22float2(sH2[er * PTS + p * BLK + t]);
            const ulonglong2* __restrict__ r0 =
                (const ulonglong2*)&sW0[(2 * er) * HID + 32 * s];
            const ulonglong2* __restrict__ r1 =
                (const ulonglong2*)&sW0[(2 * er + 1) * HID + 32 * s];
#pragma unroll
            for (int j = 0; j < 8; j++) {
                const ulonglong2 v0 = r0[j];
                const ulonglong2 v1 = r1[j];
#pragma unroll
                for (int p = 0; p < 2; p++) {
                    const u64 a0 = pk2(e[p].x, e[p].x), a1 = pk2(e[p].y, e[p].y);
                    acc[p][2 * j]     = ffma2(a1, v1.x, ffma2(a0, v0.x, acc[p][2 * j]));
                    acc[p][2 * j + 1] = ffma2(a1, v1.y, ffma2(a0, v0.y, acc[p][2 * j + 1]));
                }
            }
        }

        // ReLU -> h chunk into sH2 (own columns only; chunk1 overwrites dead enc)
        const int rbase = (s == 0) ? 16 : 0;
#pragma unroll
        for (int j = 0; j < 16; j++) {
#pragma unroll
            for (int p = 0; p < 2; p++) {
                float a, b; upk2(acc[p][j], a, b);
                sH2[(rbase + j) * PTS + p * BLK + t] =
                    __floats2half2_rn(fmaxf(a, 0.0f), fmaxf(b, 0.0f));
            }
        }
    }

    // ================= layer 1 + layer 2: 2 output chunks =================
    float res[2] = {0.0f, 0.0f};
    const float2* w2p = (const float2*)sW2;
#pragma unroll 1
    for (int s = 0; s < 2; s++) {
#pragma unroll
        for (int p = 0; p < 2; p++)
#pragma unroll
            for (int j = 0; j < 16; j++) acc[p][j] = 0ull;

#pragma unroll 2
        for (int hr = 0; hr < HID / 2; hr++) {
            const int srow = (hr < 16) ? (16 + hr) : (hr - 16);
            float2 h[2];
#pragma unroll
            for (int p = 0; p < 2; p++)
                h[p] = __half22float2(sH2[srow * PTS + p * BLK + t]);
            const ulonglong2* __restrict__ r0 =
                (const ulonglong2*)&sW1[(2 * hr) * HID + 32 * s];
            const ulonglong2* __restrict__ r1 =
                (const ulonglong2*)&sW1[(2 * hr + 1) * HID + 32 * s];
#pragma unroll
            for (int j = 0; j < 8; j++) {
                const ulonglong2 v0 = r0[j];
                const ulonglong2 v1 = r1[j];
#pragma unroll
                for (int p = 0; p < 2; p++) {
                    const u64 a0 = pk2(h[p].x, h[p].x), a1 = pk2(h[p].y, h[p].y);
                    acc[p][2 * j]     = ffma2(a1, v1.x, ffma2(a0, v0.x, acc[p][2 * j]));
                    acc[p][2 * j + 1] = ffma2(a1, v1.y, ffma2(a0, v0.y, acc[p][2 * j + 1]));
                }
            }
        }

        // layer 2 partial for this chunk
#pragma unroll
        for (int j = 0; j < 16; j++) {
            const float2 w = w2p[16 * s + j];
#pragma unroll
            for (int p = 0; p < 2; p++) {
                float a, b; upk2(acc[p][j], a, b);
                res[p] = fmaf(fmaxf(a, 0.0f), w.x, res[p]);
                res[p] = fmaf(fmaxf(b, 0.0f), w.y, res[p]);
            }
        }
    }

    if (origA >= 0) out[origA] = res[0] * INV_SCALE;
    if (origB >= 0) out[origB] = res[1] * INV_SCALE;
}

static LevelParams make_params(unsigned* qtotal_out) {
    LevelParams lp;
    unsigned qoff = 0;
    for (int l = 0; l < NLEV; l++) {
        const double r = floor(16.0 * pow(1.3819, (double)l));
        const int res = (int)r;
        lp.resf[l] = (float)res;
        const unsigned s1 = (unsigned)(res + 1);
        lp.s1[l] = s1;
        lp.s2[l] = s1 * s1;
        if (l < NDENSE) {
            const unsigned cnt = s1 * s1 * s1 + s1 * s1 + s1 + 2u;
            lp.qoff[l] = qoff;
            lp.qcnt[l] = cnt;
            qoff += cnt;
        }
    }
    *qtotal_out = qoff;
    return lp;
}

extern "C" void kernel_launch(void* const* d_in, const int* in_sizes, int n_in,
                              void* d_out, int out_size) {
    const float* x      = (const float*)d_in[0];
    const float* tables = (const float*)d_in[1];
    const float* W0     = (const float*)d_in[2];
    const float* W1     = (const float*)d_in[3];
    const float* W2     = (const float*)d_in[4];
    float* out = (float*)d_out;

    const int npts = out_size;
    unsigned qtotal = 0;
    LevelParams lp = make_params(&qtotal);

    static void* hist_addr = nullptr;
    if (!hist_addr) cudaGetSymbolAddress(&hist_addr, g_hist);

    // 24.25KB weights + 64KB sH => 88.25KB; 2 CTAs x 256 thr = 16 warps/SM
    const int smem_bytes = (ENC * HID + HID * HID + HID) * (int)sizeof(float)
                         + (HID / 2) * PTS * (int)sizeof(__half2);
    static bool attr_set = false;
    if (!attr_set) {
        cudaFuncSetAttribute(sdf_fused, cudaFuncAttributeMaxDynamicSharedMemorySize,
                             smem_bytes);
        attr_set = true;
    }

    cudaMemsetAsync(hist_addr, 0, NBINS * sizeof(int), 0);

    // 1: fused morton histogram + dense pair tables
    {
        const unsigned total = (unsigned)npts > qtotal ? (unsigned)npts : qtotal;
        bin_and_buildq<<<(total + 255) / 256, 256>>>(x, (const float2*)tables, lp,
                                                     npts, qtotal);
    }
    // 2: prefix sum
    scan_bins<<<1, 1024>>>();
    // 3: scatter (deterministic output: per-point results independent of
    //    intra-bin order)
    scatter_points<<<(npts + 255) / 256, 256>>>(x, npts);
    // 4: fused main
    const int grid = (npts + PTS - 1) / PTS;
    sdf_fused<<<grid, BLK, smem_bytes>>>(tables, W0, W1, W2, out, npts, lp);
}

// round 17
// speedup vs baseline: 3.1501x; 1.0045x over previous
#include <cuda_runtime.h>
#include <cuda_fp16.h>
#include <cmath>
#include <stdint.h>

#define NLEV   16
#define NDENSE 5
#define TSIZE  (1u << 19)
#define HID    64
#define ENC    32
#define P2     2654435761u
#define P3     805459861u
#define NMAX   1048576
#define NBINS  32768

#define BLK    256          // threads per CTA
#define PTS    512          // points per CTA (2 per thread)
#define SCALE_F    8192.0f  // 2^13: enc/h stored scaled in fp16
#define INV_SCALE  (1.0f / 8192.0f)

typedef unsigned long long u64;

// ---- device scratch (static, no runtime allocation) ----
#define QCAP 339072
__device__ float4 g_Q[QCAP];          // dense-level x-pair tables
__device__ int    g_hist[NBINS];      // morton histogram / running offsets
__device__ float4 g_xs[NMAX];         // sorted (x01, y01, z01, orig_idx)

struct LevelParams {
    float    resf[NLEV];
    unsigned s1[NLEV];
    unsigned s2[NLEV];
    unsigned qoff[NDENSE];
    unsigned qcnt[NDENSE];
};

__device__ __forceinline__ u64 pk2(float a, float b) {
    u64 r; asm("mov.b64 %0, {%1,%2};" : "=l"(r) : "f"(a), "f"(b)); return r;
}
__device__ __forceinline__ void upk2(u64 v, float& a, float& b) {
    asm("mov.b64 {%0,%1}, %2;" : "=f"(a), "=f"(b) : "l"(v));
}
// Blackwell packed fp32 FMA (FFMA2), only reachable via PTX.
__device__ __forceinline__ u64 ffma2(u64 a, u64 b, u64 c) {
    u64 d; asm("fma.rn.f32x2 %0, %1, %2, %3;" : "=l"(d) : "l"(a), "l"(b), "l"(c)); return d;
}

// ---------- morton helpers ----------
__device__ __forceinline__ unsigned part3(unsigned v) {
    v &= 31u;
    unsigned r = 0;
#pragma unroll
    for (int b = 0; b < 5; b++) r |= ((v >> b) & 1u) << (3 * b);
    return r;
}
__device__ __forceinline__ unsigned morton_bin(float x0, float y0, float z0) {
    unsigned bx = min(31, max(0, (int)floorf(x0 * 32.0f)));
    unsigned by = min(31, max(0, (int)floorf(y0 * 32.0f)));
    unsigned bz = min(31, max(0, (int)floorf(z0 * 32.0f)));
    return part3(bx) | (part3(by) << 1) | (part3(bz) << 2);
}

// ---------- launch 1: fused morton histogram + dense pair-table build ----------
__global__ void bin_and_buildq(const float* __restrict__ x,
                               const float2* __restrict__ tables,
                               LevelParams lp, int npts, unsigned qtotal) {
    const unsigned i = blockIdx.x * blockDim.x + threadIdx.x;
    if (i < qtotal) {
        int l = 0; unsigned base = 0;
#pragma unroll
        for (int k = 0; k < NDENSE; k++) {
            unsigned o = lp.qoff[k];
            if (i >= o && i < o + lp.qcnt[k]) { l = k; base = o; }
        }
        const unsigned j = i - base;
        const float2* __restrict__ tab = tables + (size_t)l * TSIZE;
        float2 a = __ldg(&tab[j]);
        float2 b = __ldg(&tab[j + 1]);
        g_Q[i] = make_float4(a.x, a.y, b.x, b.y);
    }
    if ((int)i < npts) {
        float x0 = (x[3 * i + 0] + 1.0f) * 0.5f;
        float y0 = (x[3 * i + 1] + 1.0f) * 0.5f;
        float z0 = (x[3 * i + 2] + 1.0f) * 0.5f;
        atomicAdd(&g_hist[morton_bin(x0, y0, z0)], 1);
    }
}

// ---------- launch 2: exclusive prefix sum over NBINS ----------
__global__ void scan_bins() {
    __shared__ int warp_tot[32];
    const int t = threadIdx.x;
    const int base = t * (NBINS / 1024);
    int loc[NBINS / 1024];
    int ts = 0;
#pragma unroll
    for (int k = 0; k < NBINS / 1024; k++) { loc[k] = g_hist[base + k]; ts += loc[k]; }
    int v = ts;
    for (int d = 1; d < 32; d <<= 1) {
        int n = __shfl_up_sync(0xffffffffu, v, d);
        if ((t & 31) >= d) v += n;
    }
    if ((t & 31) == 31) warp_tot[t >> 5] = v;
    __syncthreads();
    if (t < 32) {
        int w = warp_tot[t];
        for (int d = 1; d < 32; d <<= 1) {
            int n = __shfl_up_sync(0xffffffffu, w, d);
            if (t >= d) w += n;
        }
        warp_tot[t] = w;
    }
    __syncthreads();
    int excl = v - ts + ((t >> 5) ? warp_tot[(t >> 5) - 1] : 0);
    int run = excl;
#pragma unroll
    for (int k = 0; k < NBINS / 1024; k++) { g_hist[base + k] = run; run += loc[k]; }
}

// ---------- launch 3: scatter ----------
__global__ void scatter_points(const float* __restrict__ x, int npts) {
    int p = blockIdx.x * blockDim.x + threadIdx.x;
    if (p >= npts) return;
    float x0 = (x[3 * p + 0] + 1.0f) * 0.5f;
    float y0 = (x[3 * p + 1] + 1.0f) * 0.5f;
    float z0 = (x[3 * p + 2] + 1.0f) * 0.5f;
    int pos = atomicAdd(&g_hist[morton_bin(x0, y0, z0)], 1);
    g_xs[pos] = make_float4(x0, y0, z0, __int_as_float(p));
}

// ---------- hashed-level issue/consume split ----------
__device__ __forceinline__ void hashed_issue(
    float x0, float y0, float z0, float rf,
    const float2* __restrict__ tab2, const float4* __restrict__ tab4, unsigned m,
    float& fx, float& fy, float& fz, float4 q[4], unsigned& sel)
{
    const float px = x0 * rf, py = y0 * rf, pz = z0 * rf;
    const float fpx = floorf(px), fpy = floorf(py), fpz = floorf(pz);
    fx = px - fpx; fy = py - fpy; fz = pz - fpz;
    const unsigned cx = (unsigned)fpx;
    const unsigned ay = (unsigned)fpy * P2, az = (unsigned)fpz * P3;
    const unsigned s[4] = {ay ^ az, ay ^ (az + P3),
                           (ay + P2) ^ az, (ay + P2) ^ (az + P3)};
    sel = 0u;
    if ((cx & 1u) == 0u) {
#pragma unroll
        for (int j = 0; j < 4; j++) {
            const unsigned i0 = (cx ^ s[j]) & m;
            q[j] = __ldg(&tab4[i0 >> 1]);
            sel |= (i0 & 1u) << j;
        }
    } else {
        const unsigned cx1 = cx + 1u;
#pragma unroll
        for (int j = 0; j < 4; j++) {
            const float2 a = __ldg(&tab2[(cx ^ s[j]) & m]);
            const float2 b = __ldg(&tab2[(cx1 ^ s[j]) & m]);
            q[j] = make_float4(a.x, a.y, b.x, b.y);
        }
    }
}

// Consume: hi/lo selects deferred here; enc written SCALED into fp16 smem.
__device__ __forceinline__ void hashed_consume(
    float fx, float fy, float fz, const float4 q[4], unsigned sel,
    __half2* __restrict__ dst)
{
    const float gxS = (1.0f - fx) * SCALE_F, fxS = fx * SCALE_F;
    const float gy = 1.0f - fy, gz = 1.0f - fz;
    const float wyz[4] = {gy * gz, gy * fz, fy * gz, fy * fz};
    float e0 = 0.0f, e1 = 0.0f;
#pragma unroll
    for (int j = 0; j < 4; j++) {
        const bool hi = (sel >> j) & 1u;
        const float a0 = hi ? q[j].z : q[j].x;
        const float a1 = hi ? q[j].w : q[j].y;
        const float b0 = hi ? q[j].x : q[j].z;
        const float b1 = hi ? q[j].y : q[j].w;
        const float w0 = wyz[j] * gxS, w1 = wyz[j] * fxS;
        e0 = fmaf(w0, a0, fmaf(w1, b0, e0));
        e1 = fmaf(w0, a1, fmaf(w1, b1, e1));
    }
    *dst = __floats2half2_rn(e0, e1);
}

// ---- launch 4: main fused (256 thr, 2 pts/thread gather; lane-pair MLP:
//      pair of lanes processes 4 points, parity picks 16-col output chunk) ----
__global__ void __launch_bounds__(BLK, 2) sdf_fused(
    const float* __restrict__ tables,
    const float* __restrict__ W0,
    const float* __restrict__ W1,
    const float* __restrict__ W2,
    float* __restrict__ out,
    int npts, LevelParams lp)
{
    extern __shared__ __align__(16) float smem[];
    float*   sW0 = smem;                       // 2048 floats
    float*   sW1 = sW0 + ENC * HID;            // 4096
    float*   sW2 = sW1 + HID * HID;            // 64
    __half2* sH2 = (__half2*)(sW2 + HID);      // 32 rows x 512 half2 = 64KB

    {
        int t = threadIdx.x;
        float4*       s0 = (float4*)sW0;  const float4* g0 = (const float4*)W0;
        for (int i = t; i < ENC * HID / 4; i += BLK) s0[i] = g0[i];
        float4*       s1 = (float4*)sW1;  const float4* g1 = (const float4*)W1;
        for (int i = t; i < HID * HID / 4; i += BLK) s1[i] = g1[i];
        if (t < HID / 4) ((float4*)sW2)[t] = ((const float4*)W2)[t];
    }
    __syncthreads();

    const int t = threadIdx.x;
    const int base = blockIdx.x * PTS;
    const int ptA = base + t;
    const int ptB = base + BLK + t;
    const bool vA = ptA < npts, vB = ptB < npts;

    const float4 xsA = g_xs[vA ? ptA : 0];
    const float4 xsB = g_xs[vB ? ptB : 0];
    const int origA = vA ? __float_as_int(xsA.w) : -1;
    const int origB = vB ? __float_as_int(xsB.w) : -1;
    const float xA = xsA.x, yA = xsA.y, zA = xsA.z;
    const float xB = xsB.x, yB = xsB.y, zB = xsB.z;

    // ================= dense levels: A+B interleaved per level =================
#pragma unroll
    for (int l = 0; l < NDENSE; l++) {
        const float rf = lp.resf[l];
        const unsigned s1 = lp.s1[l], s2 = lp.s2[l];
        const float4* __restrict__ Q = g_Q + lp.qoff[l];

        const float pxA = xA * rf, pyA = yA * rf, pzA = zA * rf;
        const float fpxA = floorf(pxA), fpyA = floorf(pyA), fpzA = floorf(pzA);
        const float fxA = pxA - fpxA, fyA = pyA - fpyA, fzA = pzA - fpzA;
        const unsigned bA0 = (unsigned)fpxA + (unsigned)fpyA * s1 + (unsigned)fpzA * s2;
        const float pxB = xB * rf, pyB = yB * rf, pzB = zB * rf;
        const float fpxB = floorf(pxB), fpyB = floorf(pyB), fpzB = floorf(pzB);
        const float fxB = pxB - fpxB, fyB = pyB - fpyB, fzB = pzB - fpzB;
        const unsigned bB0 = (unsigned)fpxB + (unsigned)fpyB * s1 + (unsigned)fpzB * s2;

        const unsigned bbA[4] = {bA0, bA0 + s2, bA0 + s1, bA0 + s1 + s2};
        const unsigned bbB[4] = {bB0, bB0 + s2, bB0 + s1, bB0 + s1 + s2};

        float4 qA[4], qB[4];
#pragma unroll
        for (int j = 0; j < 4; j++) qA[j] = __ldg(&Q[bbA[j]]);
#pragma unroll
        for (int j = 0; j < 4; j++) qB[j] = __ldg(&Q[bbB[j]]);

        {
            const float gxS = (1.0f - fxA) * SCALE_F, fxS = fxA * SCALE_F;
            const float gy = 1.0f - fyA, gz = 1.0f - fzA;
            const float wyz[4] = {gy * gz, gy * fzA, fyA * gz, fyA * fzA};
            float e0 = 0.0f, e1 = 0.0f;
#pragma unroll
            for (int j = 0; j < 4; j++) {
                const float w0 = wyz[j] * gxS, w1 = wyz[j] * fxS;
                e0 = fmaf(w0, qA[j].x, fmaf(w1, qA[j].z, e0));
                e1 = fmaf(w0, qA[j].y, fmaf(w1, qA[j].w, e1));
            }
            sH2[l * PTS + t] = __floats2half2_rn(e0, e1);
        }
        {
            const float gxS = (1.0f - fxB) * SCALE_F, fxS = fxB * SCALE_F;
            const float gy = 1.0f - fyB, gz = 1.0f - fzB;
            const float wyz[4] = {gy * gz, gy * fzB, fyB * gz, fyB * fzB};
            float e0 = 0.0f, e1 = 0.0f;
#pragma unroll
            for (int j = 0; j < 4; j++) {
                const float w0 = wyz[j] * gxS, w1 = wyz[j] * fxS;
                e0 = fmaf(w0, qB[j].x, fmaf(w1, qB[j].z, e0));
                e1 = fmaf(w0, qB[j].y, fmaf(w1, qB[j].w, e1));
            }
            sH2[l * PTS + BLK + t] = __floats2half2_rn(e0, e1);
        }
    }

    // ========== hashed levels: single level, A+B interleaved (8 loads in flight) ====
    {
        const unsigned m = TSIZE - 1u;
#pragma unroll 1
        for (int l = NDENSE; l < NLEV; l++) {
            const float rf = lp.resf[l];
            const float2* __restrict__ t2 = ((const float2*)tables) + (size_t)l * TSIZE;
            const float4* __restrict__ t4 = (const float4*)t2;

            float fxA0, fyA0, fzA0, fxB0, fyB0, fzB0;
            float4 qA0[4], qB0[4];
            unsigned sA0, sB0;

            hashed_issue(xA, yA, zA, rf, t2, t4, m, fxA0, fyA0, fzA0, qA0, sA0);
            hashed_issue(xB, yB, zB, rf, t2, t4, m, fxB0, fyB0, fzB0, qB0, sB0);

            hashed_consume(fxA0, fyA0, fzA0, qA0, sA0, &sH2[l * PTS + t]);
            hashed_consume(fxB0, fyB0, fzB0, qB0, sB0, &sH2[l * PTS + BLK + t]);
        }
    }

    // All enc columns read below belong to this warp's lanes -> warp sync suffices.
    __syncwarp();

    // ================= MLP: lane-pair split =================
    // Pair (t, t^1) jointly processes 4 points (cols pb, pb+1, 256+pb, 256+pb+1);
    // parity owns a 16-col output chunk per pass (2 passes cover 64 outputs).
    const int par = t & 1;
    const int pb  = t & ~1;
    const int c0 = pb, c1 = pb + 1, c2 = BLK + pb, c3 = BLK + pb + 1;

    u64 acc[4][8];
    float res[4] = {0.0f, 0.0f, 0.0f, 0.0f};

    // ---- layer 0 ----
#pragma unroll 1
    for (int s = 0; s < 2; s++) {
        const int obase = 32 * s + 16 * par;
#pragma unroll
        for (int p = 0; p < 4; p++)
#pragma unroll
            for (int k = 0; k < 8; k++) acc[p][k] = 0ull;

#pragma unroll 2
        for (int er = 0; er < ENC / 2; er++) {
            const float2 e0v = __half22float2(sH2[er * PTS + c0]);
            const float2 e1v = __half22float2(sH2[er * PTS + c1]);
            const float2 e2v = __half22float2(sH2[er * PTS + c2]);
            const float2 e3v = __half22float2(sH2[er * PTS + c3]);
            const float2 ev[4] = {e0v, e1v, e2v, e3v};
            const ulonglong2* __restrict__ r0 =
                (const ulonglong2*)&sW0[(2 * er) * HID + obase];
            const ulonglong2* __restrict__ r1 =
                (const ulonglong2*)&sW0[(2 * er + 1) * HID + obase];
#pragma unroll
            for (int j = 0; j < 4; j++) {
                const ulonglong2 v0 = r0[j];
                const ulonglong2 v1 = r1[j];
#pragma unroll
                for (int p = 0; p < 4; p++) {
                    const u64 a0 = pk2(ev[p].x, ev[p].x), a1 = pk2(ev[p].y, ev[p].y);
                    acc[p][2 * j]     = ffma2(a1, v1.x, ffma2(a0, v0.x, acc[p][2 * j]));
                    acc[p][2 * j + 1] = ffma2(a1, v1.y, ffma2(a0, v0.y, acc[p][2 * j + 1]));
                }
            }
        }

        // Pair lanes may drift: ensure both finished reading enc before pass-1
        // stores overwrite enc rows.
        __syncwarp();

        // ReLU -> h: half2 rows 16s+8par+k mapped to smem rows (16-16s)+8par+k
        const int rbase = (16 - 16 * s) + 8 * par;
        const int cols[4] = {c0, c1, c2, c3};
#pragma unroll
        for (int k = 0; k < 8; k++) {
#pragma unroll
            for (int p = 0; p < 4; p++) {
                float a, b; upk2(acc[p][k], a, b);
                sH2[(rbase + k) * PTS + cols[p]] =
                    __floats2half2_rn(fmaxf(a, 0.0f), fmaxf(b, 0.0f));
            }
        }
    }
    __syncwarp();   // h written by both parities before layer 1 reads

    // ---- layer 1 + layer 2 ----
    const float2* w2p = (const float2*)sW2;
#pragma unroll 1
    for (int s = 0; s < 2; s++) {
        const int obase = 32 * s + 16 * par;
#pragma unroll
        for (int p = 0; p < 4; p++)
#pragma unroll
            for (int k = 0; k < 8; k++) acc[p][k] = 0ull;

#pragma unroll 2
        for (int hr = 0; hr < HID / 2; hr++) {
            const int srow = (hr < 16) ? (16 + hr) : (hr - 16);
            const float2 h0v = __half22float2(sH2[srow * PTS + c0]);
            const float2 h1v = __half22float2(sH2[srow * PTS + c1]);
            const float2 h2v = __half22float2(sH2[srow * PTS + c2]);
            const float2 h3v = __half22float2(sH2[srow * PTS + c3]);
            const float2 hv[4] = {h0v, h1v, h2v, h3v};
            const ulonglong2* __restrict__ r0 =
                (const ulonglong2*)&sW1[(2 * hr) * HID + obase];
            const ulonglong2* __restrict__ r1 =
                (const ulonglong2*)&sW1[(2 * hr + 1) * HID + obase];
#pragma unroll
            for (int j = 0; j < 4; j++) {
                const ulonglong2 v0 = r0[j];
                const ulonglong2 v1 = r1[j];
#pragma unroll
                for (int p = 0; p < 4; p++) {
                    const u64 a0 = pk2(hv[p].x, hv[p].x), a1 = pk2(hv[p].y, hv[p].y);
                    acc[p][2 * j]     = ffma2(a1, v1.x, ffma2(a0, v0.x, acc[p][2 * j]));
                    acc[p][2 * j + 1] = ffma2(a1, v1.y, ffma2(a0, v0.y, acc[p][2 * j + 1]));
                }
            }
        }

        // layer 2 partial: acc[p][k] = outputs (obase+2k, obase+2k+1)
#pragma unroll
        for (int k = 0; k < 8; k++) {
            const float2 w = w2p[obase / 2 + k];
#pragma unroll
            for (int p = 0; p < 4; p++) {
                float a, b; upk2(acc[p][k], a, b);
                res[p] = fmaf(fmaxf(a, 0.0f), w.x, res[p]);
                res[p] = fmaf(fmaxf(b, 0.0f), w.y, res[p]);
            }
        }
    }

    // combine the two parity partials; this thread's own points are p=par, p=2+par
#pragma unroll
    for (int p = 0; p < 4; p++)
        res[p] += __shfl_xor_sync(0xffffffffu, res[p], 1);

    if (origA >= 0) out[origA] = res[par] * INV_SCALE;
    if (origB >= 0) out[origB] = res[2 + par] * INV_SCALE;
}

static LevelParams make_params(unsigned* qtotal_out) {
    LevelParams lp;
    unsigned qoff = 0;
    for (int l = 0; l < NLEV; l++) {
        const double r = floor(16.0 * pow(1.3819, (double)l));
        const int res = (int)r;
        lp.resf[l] = (float)res;
        const unsigned s1 = (unsigned)(res + 1);
        lp.s1[l] = s1;
        lp.s2[l] = s1 * s1;
        if (l < NDENSE) {
            const unsigned cnt = s1 * s1 * s1 + s1 * s1 + s1 + 2u;
            lp.qoff[l] = qoff;
            lp.qcnt[l] = cnt;
            qoff += cnt;
        }
    }
    *qtotal_out = qoff;
    return lp;
}

extern "C" void kernel_launch(void* const* d_in, const int* in_sizes, int n_in,
                              void* d_out, int out_size) {
    const float* x      = (const float*)d_in[0];
    const float* tables = (const float*)d_in[1];
    const float* W0     = (const float*)d_in[2];
    const float* W1     = (const float*)d_in[3];
    const float* W2     = (const float*)d_in[4];
    float* out = (float*)d_out;

    const int npts = out_size;
    unsigned qtotal = 0;
    LevelParams lp = make_params(&qtotal);

    static void* hist_addr = nullptr;
    if (!hist_addr) cudaGetSymbolAddress(&hist_addr, g_hist);

    // 24.25KB weights + 64KB sH => 88.25KB; 2 CTAs x 256 thr = 16 warps/SM
    const int smem_bytes = (ENC * HID + HID * HID + HID) * (int)sizeof(float)
                         + (HID / 2) * PTS * (int)sizeof(__half2);
    static bool attr_set = false;
    if (!attr_set) {
        cudaFuncSetAttribute(sdf_fused, cudaFuncAttributeMaxDynamicSharedMemorySize,
                             smem_bytes);
        attr_set = true;
    }

    cudaMemsetAsync(hist_addr, 0, NBINS * sizeof(int), 0);

    // 1: fused morton histogram + dense pair tables
    {
        const unsigned total = (unsigned)npts > qtotal ? (unsigned)npts : qtotal;
        bin_and_buildq<<<(total + 255) / 256, 256>>>(x, (const float2*)tables, lp,
                                                     npts, qtotal);
    }
    // 2: prefix sum
    scan_bins<<<1, 1024>>>();
    // 3: scatter (deterministic output: per-point results independent of
    //    intra-bin order)
    scatter_points<<<(npts + 255) / 256, 256>>>(x, npts);
    // 4: fused main
    const int grid = (npts + PTS - 1) / PTS;
    sdf_fused<<<grid, BLK, smem_bytes>>>(tables, W0, W1, W2, out, npts, lp);
}